// round 4
// baseline (speedup 1.0000x reference)
#include <cuda_runtime.h>

#define BB 128
#define NT 64    // n1: templates
#define NM 128   // n2: label points

// scratch (device globals are sanctioned for scratch)
__device__ float g_gpool[BB * 32 * NM];
__device__ float g_h2[BB * 32 * NM];

// ---------------------------------------------------------------------------
// Kernel 1: global-attention branch -> g_gpool (B,32,NM)
// grid 512 = B*4 m-tiles of 32. block 128 = 4 warps; warp w handles
// m_local = w*8+mi (mi=0..7); lane = output channel o; 4 n-pixels per chunk.
// Per-thread state is scalars only -> no local memory possible.
// ---------------------------------------------------------------------------
__global__ __launch_bounds__(128) void k_gpool(
    const float* __restrict__ x_label, const float* __restrict__ x_object,
    const float* __restrict__ template_xyz,
    const float* __restrict__ gw_w1, const float* __restrict__ gw_b1,
    const float* __restrict__ gw_s,  const float* __restrict__ gw_t,
    const float* __restrict__ gw_w2, const float* __restrict__ gw_b2,
    const float* __restrict__ gm_w1, const float* __restrict__ gm_s1,
    const float* __restrict__ gm_t1, const float* __restrict__ gm_w2,
    const float* __restrict__ gm_s2, const float* __restrict__ gm_t2)
{
    __shared__ float xoT[64][33];   // [n][c], padded
    __shared__ float Bn[64][33];    // [n][o] = -s*(W1@xo), padded
    __shared__ float Tn[64][33];    // [n][o] gm1 xyz part + t1, padded
    __shared__ float As[32][33];    // [ml][o] = s*(W1@xl + b1) + t, padded
    __shared__ float W2s[32][32];   // [c][o]
    __shared__ float Wm1s[32][32];  // [c][o] scaled
    __shared__ float Wm2s[32][32];  // [c][o] scaled
    __shared__ float xls[32][32];   // [c][ml] staging
    __shared__ __align__(16) float buf[4][32][4];  // per-warp exchange
    __shared__ float b2s[32], ct2s[32];

    const int tid = threadIdx.x;
    const int b = blockIdx.x >> 2, mt = blockIdx.x & 3;

    // ---- phase 1: stage inputs + weights ----
    for (int i = tid; i < 2048; i += 128) {          // x_object (32,64)
        int c = i >> 6, n = i & 63;
        xoT[n][c] = x_object[(size_t)b * 2048 + i];
    }
    for (int i = tid; i < 1024; i += 128) {          // x_label slice (32,32)
        int c = i >> 5, ml = i & 31;
        xls[c][ml] = x_label[(size_t)b * 4096 + c * 128 + mt * 32 + ml];
    }
    for (int i = tid; i < 1024; i += 128) {
        int c = i >> 5, o = i & 31;
        W2s[c][o]  = gw_w2[o * 32 + c];
        Wm1s[c][o] = gm_s1[o] * gm_w1[o * 35 + 3 + c];
        Wm2s[c][o] = gm_s2[o] * gm_w2[o * 32 + c];
    }
    if (tid < 32) { b2s[tid] = gw_b2[tid]; ct2s[tid] = gm_t2[tid]; }
    __syncthreads();

    // ---- phase 2: per-(b,n) and per-(b,m) precompute ----
    for (int i = tid; i < 2048; i += 128) {          // o-major: weight broadcast
        int o = i >> 6, n = i & 63;
        float a = 0.f;
        #pragma unroll
        for (int c = 0; c < 32; c++) a += gw_w1[o * 32 + c] * xoT[n][c];
        Bn[n][o] = -gw_s[o] * a;
        const float* tx = template_xyz + (size_t)b * 192 + n * 3;
        Tn[n][o] = gm_s1[o] * (gm_w1[o * 35] * tx[0] + gm_w1[o * 35 + 1] * tx[1] +
                               gm_w1[o * 35 + 2] * tx[2]) + gm_t1[o];
    }
    for (int i = tid; i < 1024; i += 128) {
        int o = i >> 5, ml = i & 31;
        float a = 0.f;
        #pragma unroll
        for (int c = 0; c < 32; c++) a += gw_w1[o * 32 + c] * xls[c][ml];
        As[ml][o] = gw_s[o] * a + gw_s[o] * gw_b1[o] + gw_t[o];
    }
    __syncthreads();

    // ---- main loop ----
    const int w = tid >> 5, o = tid & 31;
    float4* mybuf = (float4*)&buf[w][o][0];

    #pragma unroll 1
    for (int mi = 0; mi < 8; mi++) {
        const int ml = w * 8 + mi;
        const float as = As[ml][o];
        float um = 0.f;

        #pragma unroll 1
        for (int j = 0; j < 16; j++) {
            const int n0 = 4 * j;

            // stage gw1 (folded): leaky(as + Bn[n][o])
            float z0 = as + Bn[n0 + 0][o];
            float z1 = as + Bn[n0 + 1][o];
            float z2 = as + Bn[n0 + 2][o];
            float z3 = as + Bn[n0 + 3][o];
            __syncwarp();
            *mybuf = make_float4(fmaxf(z0, 0.2f * z0), fmaxf(z1, 0.2f * z1),
                                 fmaxf(z2, 0.2f * z2), fmaxf(z3, 0.2f * z3));
            __syncwarp();

            // stage gw2: q = b2 + W2 @ lv
            float q0 = b2s[o], q1 = q0, q2 = q0, q3 = q0;
            #pragma unroll
            for (int c = 0; c < 32; c++) {
                float4 v = *(const float4*)&buf[w][c][0];
                float ww = W2s[c][o];
                q0 += ww * v.x; q1 += ww * v.y; q2 += ww * v.z; q3 += ww * v.w;
            }

            // gate: g = sigmoid(q) * xo[o][n]
            float g0 = __fdividef(xoT[n0 + 0][o], 1.f + __expf(-q0));
            float g1 = __fdividef(xoT[n0 + 1][o], 1.f + __expf(-q1));
            float g2 = __fdividef(xoT[n0 + 2][o], 1.f + __expf(-q2));
            float g3 = __fdividef(xoT[n0 + 3][o], 1.f + __expf(-q3));
            __syncwarp();
            *mybuf = make_float4(g0, g1, g2, g3);
            __syncwarp();

            // stage gm1: t = Tn + Wm1 @ g, relu
            float t0 = Tn[n0 + 0][o];
            float t1 = Tn[n0 + 1][o];
            float t2 = Tn[n0 + 2][o];
            float t3 = Tn[n0 + 3][o];
            #pragma unroll
            for (int c = 0; c < 32; c++) {
                float4 v = *(const float4*)&buf[w][c][0];
                float ww = Wm1s[c][o];
                t0 += ww * v.x; t1 += ww * v.y; t2 += ww * v.z; t3 += ww * v.w;
            }
            __syncwarp();
            *mybuf = make_float4(fmaxf(t0, 0.f), fmaxf(t1, 0.f),
                                 fmaxf(t2, 0.f), fmaxf(t3, 0.f));
            __syncwarp();

            // stage gm2: u = t2bias + Wm2 @ r ; fold relu+max into um
            float u0 = ct2s[o], u1 = u0, u2 = u0, u3 = u0;
            #pragma unroll
            for (int c = 0; c < 32; c++) {
                float4 v = *(const float4*)&buf[w][c][0];
                float ww = Wm2s[c][o];
                u0 += ww * v.x; u1 += ww * v.y; u2 += ww * v.z; u3 += ww * v.w;
            }
            um = fmaxf(um, fmaxf(fmaxf(u0, u1), fmaxf(u2, u3)));
        }

        g_gpool[((size_t)b * 32 + o) * NM + mt * 32 + ml] = um;
    }
}

// ---------------------------------------------------------------------------
// Kernel 2a: cosine sim + argmax gather + 2-layer MLP -> g_h2 (B,32,NM)
// grid B, block NM (thread = m). Only 32-float arrays, all const-indexed.
// ---------------------------------------------------------------------------
__global__ __launch_bounds__(128) void k_out_a(
    const float* __restrict__ x_label, const float* __restrict__ x_object,
    const float* __restrict__ template_xyz,
    const float* __restrict__ mlp_w1, const float* __restrict__ mlp_s1,
    const float* __restrict__ mlp_t1, const float* __restrict__ mlp_w2,
    const float* __restrict__ mlp_s2, const float* __restrict__ mlp_t2)
{
    __shared__ float xo_s[32][64];
    __shared__ float w1T[68][32];
    __shared__ float w2T[32][32];
    __shared__ float na_s[64];

    const int b = blockIdx.x, tid = threadIdx.x, m = tid;

    for (int i = tid; i < 2048; i += 128)
        ((float*)xo_s)[i] = x_object[(size_t)b * 2048 + i];
    for (int i = tid; i < 68 * 32; i += 128) {
        int j = i >> 5, o = i & 31;
        w1T[j][o] = mlp_w1[o * 68 + j];
    }
    for (int i = tid; i < 1024; i += 128) {
        int c = i >> 5, o = i & 31;
        w2T[c][o] = mlp_w2[o * 32 + c];
    }
    __syncthreads();
    if (tid < 64) {
        float s = 0.f;
        #pragma unroll
        for (int c = 0; c < 32; c++) { float v = xo_s[c][tid]; s += v * v; }
        na_s[tid] = sqrtf(s);
    }

    float xl[32];
    #pragma unroll
    for (int c = 0; c < 32; c++)
        xl[c] = x_label[(size_t)b * 4096 + c * 128 + m];
    float nb = 0.f;
    #pragma unroll
    for (int c = 0; c < 32; c++) nb += xl[c] * xl[c];
    nb = sqrtf(nb);
    __syncthreads();

    // argmax over templates (cos also max-pooled -> best)
    float best = -3.4e38f; int bidx = 0;
    #pragma unroll 1
    for (int n = 0; n < 64; n++) {
        float num = 0.f;
        #pragma unroll
        for (int c = 0; c < 32; c++) num += xo_s[c][n] * xl[c];
        float cs = num / fmaxf(na_s[n] * nb, 1e-8f);
        if (cs > best) { best = cs; bidx = n; }
    }

    // h = relu(s1*(W1 @ [best, txyz, xo[:,bidx], xl]) + t1)
    float h[32];
    #pragma unroll
    for (int o = 0; o < 32; o++) h[o] = w1T[0][o] * best;
    {
        const float* tx = template_xyz + (size_t)b * 192 + bidx * 3;
        float a0 = tx[0], a1 = tx[1], a2 = tx[2];
        #pragma unroll
        for (int o = 0; o < 32; o++)
            h[o] += w1T[1][o] * a0 + w1T[2][o] * a1 + w1T[3][o] * a2;
    }
    #pragma unroll
    for (int c = 0; c < 32; c++) {
        float xoc = xo_s[c][bidx];
        #pragma unroll
        for (int o = 0; o < 32; o++) h[o] += w1T[4 + c][o] * xoc;
    }
    #pragma unroll
    for (int c = 0; c < 32; c++) {
        float v = xl[c];
        #pragma unroll
        for (int o = 0; o < 32; o++) h[o] += w1T[36 + c][o] * v;
    }
    #pragma unroll
    for (int o = 0; o < 32; o++)
        h[o] = fmaxf(mlp_s1[o] * h[o] + mlp_t1[o], 0.f);

    // h2 = relu(s2*(W2 @ h) + t2) -> g_h2
    float h2[32];
    #pragma unroll
    for (int o = 0; o < 32; o++) h2[o] = 0.f;
    #pragma unroll
    for (int c = 0; c < 32; c++) {
        float v = h[c];
        #pragma unroll
        for (int o = 0; o < 32; o++) h2[o] += w2T[c][o] * v;
    }
    #pragma unroll
    for (int o = 0; o < 32; o++)
        g_h2[((size_t)b * 32 + o) * NM + m] =
            fmaxf(mlp_s2[o] * h2[o] + mlp_t2[o], 0.f);
}

// ---------------------------------------------------------------------------
// Kernel 2b: final layers. fused = [h2, gpool] (64) -> fl1 relu -> fl2 -> out
// grid B, block NM. o1 staged in shared (no dynamic per-thread arrays).
// ---------------------------------------------------------------------------
__global__ __launch_bounds__(128) void k_out_b(
    const float* __restrict__ fl_w1, const float* __restrict__ fl_s1,
    const float* __restrict__ fl_t1, const float* __restrict__ fl_w2,
    const float* __restrict__ fl_b2, float* __restrict__ out)
{
    __shared__ float o1s[64][128];   // [o][m]

    const int b = blockIdx.x, tid = threadIdx.x, m = tid;

    float hv[64];
    #pragma unroll
    for (int c = 0; c < 32; c++)
        hv[c] = g_h2[((size_t)b * 32 + c) * NM + m];
    #pragma unroll
    for (int c = 0; c < 32; c++)
        hv[32 + c] = g_gpool[((size_t)b * 32 + c) * NM + m];

    #pragma unroll 2
    for (int o = 0; o < 64; o++) {
        float acc = 0.f;
        const float4* wp = (const float4*)(fl_w1 + o * 64);
        #pragma unroll
        for (int c4 = 0; c4 < 16; c4++) {
            float4 ww = __ldg(&wp[c4]);
            acc += ww.x * hv[4 * c4] + ww.y * hv[4 * c4 + 1] +
                   ww.z * hv[4 * c4 + 2] + ww.w * hv[4 * c4 + 3];
        }
        o1s[o][m] = fmaxf(fl_s1[o] * acc + fl_t1[o], 0.f);
    }
    // each thread reads only the column it wrote -> no block sync needed,
    // but keep one for safety against compiler reordering assumptions
    __syncthreads();

    #pragma unroll 2
    for (int o = 0; o < 64; o++) {
        float acc = fl_b2[o];
        const float4* wp = (const float4*)(fl_w2 + o * 64);
        #pragma unroll
        for (int c4 = 0; c4 < 16; c4++) {
            float4 ww = __ldg(&wp[c4]);
            acc += ww.x * o1s[4 * c4 + 0][m] + ww.y * o1s[4 * c4 + 1][m] +
                   ww.z * o1s[4 * c4 + 2][m] + ww.w * o1s[4 * c4 + 3][m];
        }
        out[((size_t)b * 64 + o) * NM + m] = acc;
    }
}

extern "C" void kernel_launch(void* const* d_in, const int* in_sizes, int n_in,
                              void* d_out, int out_size)
{
    const float* x_label      = (const float*)d_in[0];
    const float* x_object     = (const float*)d_in[1];
    const float* template_xyz = (const float*)d_in[2];
    const float* mlp_w1 = (const float*)d_in[3];
    const float* mlp_s1 = (const float*)d_in[4];
    const float* mlp_t1 = (const float*)d_in[5];
    const float* mlp_w2 = (const float*)d_in[6];
    const float* mlp_s2 = (const float*)d_in[7];
    const float* mlp_t2 = (const float*)d_in[8];
    const float* gw_w1  = (const float*)d_in[9];
    const float* gw_b1  = (const float*)d_in[10];
    const float* gw_s   = (const float*)d_in[11];
    const float* gw_t   = (const float*)d_in[12];
    const float* gw_w2  = (const float*)d_in[13];
    const float* gw_b2  = (const float*)d_in[14];
    const float* gm_w1  = (const float*)d_in[15];
    const float* gm_s1  = (const float*)d_in[16];
    const float* gm_t1  = (const float*)d_in[17];
    const float* gm_w2  = (const float*)d_in[18];
    const float* gm_s2  = (const float*)d_in[19];
    const float* gm_t2  = (const float*)d_in[20];
    const float* fl_w1  = (const float*)d_in[21];
    const float* fl_s1  = (const float*)d_in[22];
    const float* fl_t1  = (const float*)d_in[23];
    const float* fl_w2  = (const float*)d_in[24];
    const float* fl_b2  = (const float*)d_in[25];

    k_gpool<<<512, 128>>>(x_label, x_object, template_xyz,
                          gw_w1, gw_b1, gw_s, gw_t, gw_w2, gw_b2,
                          gm_w1, gm_s1, gm_t1, gm_w2, gm_s2, gm_t2);
    k_out_a<<<128, 128>>>(x_label, x_object, template_xyz,
                          mlp_w1, mlp_s1, mlp_t1, mlp_w2, mlp_s2, mlp_t2);
    k_out_b<<<128, 128>>>(fl_w1, fl_s1, fl_t1, fl_w2, fl_b2, (float*)d_out);
}

// round 5
// speedup vs baseline: 1.4198x; 1.4198x over previous
#include <cuda_runtime.h>

#define BB 128
#define NT 64    // n1: templates
#define NM 128   // n2: label points

// scratch (device globals are sanctioned for scratch)
__device__ float g_gpool[BB * 32 * NM];

typedef unsigned long long ull;

__device__ __forceinline__ ull pk(float lo, float hi) {
    ull r; asm("mov.b64 %0,{%1,%2};" : "=l"(r) : "f"(lo), "f"(hi)); return r;
}
__device__ __forceinline__ ull pk1(float v) {
    ull r; asm("mov.b64 %0,{%1,%1};" : "=l"(r) : "f"(v)); return r;
}
__device__ __forceinline__ void upk(ull v, float& lo, float& hi) {
    asm("mov.b64 {%0,%1},%2;" : "=f"(lo), "=f"(hi) : "l"(v));
}
__device__ __forceinline__ ull ffma2(ull a, ull b, ull c) {
    ull d; asm("fma.rn.f32x2 %0,%1,%2,%3;" : "=l"(d) : "l"(a), "l"(b), "l"(c)); return d;
}

// ---------------------------------------------------------------------------
// Kernel 1: global-attention branch -> g_gpool (B,32,NM)
// grid 512 = B*4 m-tiles of 32. block 128 = 4 warps; warp w handles
// m_local = w*8+mi; lane = output channel o; 4 n-pixels per chunk, packed
// into f32x2 pairs. Weight columns live in registers (const-indexed).
// ---------------------------------------------------------------------------
__global__ __launch_bounds__(128) void k_gpool(
    const float* __restrict__ x_label, const float* __restrict__ x_object,
    const float* __restrict__ template_xyz,
    const float* __restrict__ gw_w1, const float* __restrict__ gw_b1,
    const float* __restrict__ gw_s,  const float* __restrict__ gw_t,
    const float* __restrict__ gw_w2, const float* __restrict__ gw_b2,
    const float* __restrict__ gm_w1, const float* __restrict__ gm_s1,
    const float* __restrict__ gm_t1, const float* __restrict__ gm_w2,
    const float* __restrict__ gm_s2, const float* __restrict__ gm_t2)
{
    __shared__ float xoT[64][33];     // [n][c] padded
    __shared__ float Bn[64][33];      // [n][o] = -s*(W1@xo)
    __shared__ float Tn[64][33];      // [n][o] gm1 xyz part + t1
    __shared__ float As[32][33];      // [ml][o] = s*(W1@xl + b1) + t
    __shared__ float Wst[3][32][32];  // staging [layer][c][o]
    __shared__ float xls[32][32];
    __shared__ __align__(16) float buf[4][32][4];  // per-warp exchange
    __shared__ float b2s[32], ct2s[32];

    const int tid = threadIdx.x;
    const int b = blockIdx.x >> 2, mt = blockIdx.x & 3;

    // ---- stage inputs + weights (coalesced) ----
    for (int i = tid; i < 2048; i += 128) {
        int c = i >> 6, n = i & 63;
        xoT[n][c] = x_object[(size_t)b * 2048 + i];
    }
    for (int i = tid; i < 1024; i += 128) {
        int c = i >> 5, ml = i & 31;
        xls[c][ml] = x_label[(size_t)b * 4096 + c * 128 + mt * 32 + ml];
    }
    for (int i = tid; i < 1024; i += 128) {
        int c = i >> 5, o = i & 31;
        Wst[0][c][o] = gw_w2[o * 32 + c];
        Wst[1][c][o] = gm_s1[o] * gm_w1[o * 35 + 3 + c];
        Wst[2][c][o] = gm_s2[o] * gm_w2[o * 32 + c];
    }
    if (tid < 32) { b2s[tid] = gw_b2[tid]; ct2s[tid] = gm_t2[tid]; }
    __syncthreads();

    // ---- per-(b,n) and per-(b,m) precompute ----
    for (int i = tid; i < 2048; i += 128) {
        int o = i >> 6, n = i & 63;
        float a = 0.f;
        #pragma unroll
        for (int c = 0; c < 32; c++) a += gw_w1[o * 32 + c] * xoT[n][c];
        Bn[n][o] = -gw_s[o] * a;
        const float* tx = template_xyz + (size_t)b * 192 + n * 3;
        Tn[n][o] = gm_s1[o] * (gm_w1[o * 35] * tx[0] + gm_w1[o * 35 + 1] * tx[1] +
                               gm_w1[o * 35 + 2] * tx[2]) + gm_t1[o];
    }
    for (int i = tid; i < 1024; i += 128) {
        int o = i >> 5, ml = i & 31;
        float a = 0.f;
        #pragma unroll
        for (int c = 0; c < 32; c++) a += gw_w1[o * 32 + c] * xls[c][ml];
        As[ml][o] = gw_s[o] * a + gw_s[o] * gw_b1[o] + gw_t[o];
    }
    __syncthreads();

    // ---- hoist weight columns into registers (const-indexed only) ----
    const int w = tid >> 5, o = tid & 31;
    float w2r[32], wm1r[32], wm2r[32];
    #pragma unroll
    for (int c = 0; c < 32; c++) {
        w2r[c]  = Wst[0][c][o];
        wm1r[c] = Wst[1][c][o];
        wm2r[c] = Wst[2][c][o];
    }
    const float bias2 = b2s[o], biasT = ct2s[o];

    float4* mybuf = (float4*)&buf[w][o][0];
    const ulonglong2* bufv = (const ulonglong2*)&buf[w][0][0];

    #pragma unroll 1
    for (int mi = 0; mi < 8; mi++) {
        const int ml = w * 8 + mi;
        const float as = As[ml][o];
        float um = 0.f;

        #pragma unroll 1
        for (int j = 0; j < 16; j++) {
            const int n0 = 4 * j;

            // stage gw1 (folded): leaky(as + Bn[n][o])
            float z0 = as + Bn[n0 + 0][o];
            float z1 = as + Bn[n0 + 1][o];
            float z2 = as + Bn[n0 + 2][o];
            float z3 = as + Bn[n0 + 3][o];
            __syncwarp();
            *mybuf = make_float4(fmaxf(z0, 0.2f * z0), fmaxf(z1, 0.2f * z1),
                                 fmaxf(z2, 0.2f * z2), fmaxf(z3, 0.2f * z3));
            __syncwarp();

            // stage gw2: q = b2 + W2 @ lv   (packed pairs)
            ull q01 = pk1(bias2), q23 = q01;
            #pragma unroll
            for (int c = 0; c < 32; c++) {
                ull wp = pk1(w2r[c]);
                ulonglong2 v = bufv[c];
                q01 = ffma2(v.x, wp, q01);
                q23 = ffma2(v.y, wp, q23);
            }

            // gate: g = sigmoid(q) * xo[n][o]
            float q0, q1, q2, q3;
            upk(q01, q0, q1); upk(q23, q2, q3);
            float g0 = __fdividef(xoT[n0 + 0][o], 1.f + __expf(-q0));
            float g1 = __fdividef(xoT[n0 + 1][o], 1.f + __expf(-q1));
            float g2 = __fdividef(xoT[n0 + 2][o], 1.f + __expf(-q2));
            float g3 = __fdividef(xoT[n0 + 3][o], 1.f + __expf(-q3));
            __syncwarp();
            *mybuf = make_float4(g0, g1, g2, g3);
            __syncwarp();

            // stage gm1: t = Tn + Wm1 @ g, relu
            ull t01 = pk(Tn[n0 + 0][o], Tn[n0 + 1][o]);
            ull t23 = pk(Tn[n0 + 2][o], Tn[n0 + 3][o]);
            #pragma unroll
            for (int c = 0; c < 32; c++) {
                ull wp = pk1(wm1r[c]);
                ulonglong2 v = bufv[c];
                t01 = ffma2(v.x, wp, t01);
                t23 = ffma2(v.y, wp, t23);
            }
            float t0, t1, t2, t3;
            upk(t01, t0, t1); upk(t23, t2, t3);
            __syncwarp();
            *mybuf = make_float4(fmaxf(t0, 0.f), fmaxf(t1, 0.f),
                                 fmaxf(t2, 0.f), fmaxf(t3, 0.f));
            __syncwarp();

            // stage gm2: u = t2 + Wm2 @ r ; relu+max folded into um
            ull u01 = pk1(biasT), u23 = u01;
            #pragma unroll
            for (int c = 0; c < 32; c++) {
                ull wp = pk1(wm2r[c]);
                ulonglong2 v = bufv[c];
                u01 = ffma2(v.x, wp, u01);
                u23 = ffma2(v.y, wp, u23);
            }
            float u0, u1, u2, u3;
            upk(u01, u0, u1); upk(u23, u2, u3);
            um = fmaxf(um, fmaxf(fmaxf(u0, u1), fmaxf(u2, u3)));
        }

        g_gpool[((size_t)b * 32 + o) * NM + mt * 32 + ml] = um;
    }
}

// ---------------------------------------------------------------------------
// Kernel 2 (fused): cosine sim + argmax gather + MLP + final layers -> out
// grid B, block NM (thread = m). Per-thread arrays const-indexed only;
// o1 staged in shared (conflict-free column access).
// ---------------------------------------------------------------------------
__global__ __launch_bounds__(128) void k_out(
    const float* __restrict__ x_label, const float* __restrict__ x_object,
    const float* __restrict__ template_xyz,
    const float* __restrict__ mlp_w1, const float* __restrict__ mlp_s1,
    const float* __restrict__ mlp_t1, const float* __restrict__ mlp_w2,
    const float* __restrict__ mlp_s2, const float* __restrict__ mlp_t2,
    const float* __restrict__ fl_w1, const float* __restrict__ fl_s1,
    const float* __restrict__ fl_t1, const float* __restrict__ fl_w2,
    const float* __restrict__ fl_b2, float* __restrict__ out)
{
    __shared__ float xo_s[32][64];
    __shared__ float w1T[68][32];
    __shared__ float w2T[32][32];
    __shared__ float na_s[64];
    __shared__ float o1s[64][128];

    const int b = blockIdx.x, tid = threadIdx.x, m = tid;

    for (int i = tid; i < 2048; i += 128)
        ((float*)xo_s)[i] = x_object[(size_t)b * 2048 + i];
    for (int i = tid; i < 68 * 32; i += 128) {
        int j = i >> 5, o = i & 31;
        w1T[j][o] = mlp_w1[o * 68 + j];
    }
    for (int i = tid; i < 1024; i += 128) {
        int c = i >> 5, o = i & 31;
        w2T[c][o] = mlp_w2[o * 32 + c];
    }
    __syncthreads();
    if (tid < 64) {
        float s = 0.f;
        #pragma unroll
        for (int c = 0; c < 32; c++) { float v = xo_s[c][tid]; s += v * v; }
        na_s[tid] = sqrtf(s);
    }

    float xl[32];
    #pragma unroll
    for (int c = 0; c < 32; c++)
        xl[c] = x_label[(size_t)b * 4096 + c * 128 + m];
    float nb = 0.f;
    #pragma unroll
    for (int c = 0; c < 32; c++) nb += xl[c] * xl[c];
    nb = sqrtf(nb);
    __syncthreads();

    // argmax over templates (cos also max-pooled -> best)
    float best = -3.4e38f; int bidx = 0;
    #pragma unroll 1
    for (int n = 0; n < 64; n++) {
        float num = 0.f;
        #pragma unroll
        for (int c = 0; c < 32; c++) num += xo_s[c][n] * xl[c];
        float cs = num / fmaxf(na_s[n] * nb, 1e-8f);
        if (cs > best) { best = cs; bidx = n; }
    }

    // h = relu(s1*(W1 @ [best, txyz, xo[:,bidx], xl]) + t1)
    float h[32];
    #pragma unroll
    for (int o = 0; o < 32; o++) h[o] = w1T[0][o] * best;
    {
        const float* tx = template_xyz + (size_t)b * 192 + bidx * 3;
        float a0 = tx[0], a1 = tx[1], a2 = tx[2];
        #pragma unroll
        for (int o = 0; o < 32; o++)
            h[o] += w1T[1][o] * a0 + w1T[2][o] * a1 + w1T[3][o] * a2;
    }
    #pragma unroll
    for (int c = 0; c < 32; c++) {
        float xoc = xo_s[c][bidx];
        #pragma unroll
        for (int o = 0; o < 32; o++) h[o] += w1T[4 + c][o] * xoc;
    }
    #pragma unroll
    for (int c = 0; c < 32; c++) {
        float v = xl[c];
        #pragma unroll
        for (int o = 0; o < 32; o++) h[o] += w1T[36 + c][o] * v;
    }
    #pragma unroll
    for (int o = 0; o < 32; o++)
        h[o] = fmaxf(mlp_s1[o] * h[o] + mlp_t1[o], 0.f);

    // h2 = relu(s2*(W2 @ h) + t2)
    float h2[32];
    #pragma unroll
    for (int o = 0; o < 32; o++) h2[o] = 0.f;
    #pragma unroll
    for (int c = 0; c < 32; c++) {
        float v = h[c];
        #pragma unroll
        for (int o = 0; o < 32; o++) h2[o] += w2T[c][o] * v;
    }
    #pragma unroll
    for (int o = 0; o < 32; o++)
        h2[o] = fmaxf(mlp_s2[o] * h2[o] + mlp_t2[o], 0.f);

    float gp[32];
    #pragma unroll
    for (int c = 0; c < 32; c++)
        gp[c] = g_gpool[((size_t)b * 32 + c) * NM + m];

    // fl1: o1 = relu(s*(W @ [h2, gp]) + t) staged in shared
    #pragma unroll 2
    for (int o = 0; o < 64; o++) {
        float acc = 0.f;
        const float4* wp = (const float4*)(fl_w1 + o * 64);
        #pragma unroll
        for (int c4 = 0; c4 < 8; c4++) {
            float4 ww = __ldg(&wp[c4]);
            acc += ww.x * h2[4 * c4] + ww.y * h2[4 * c4 + 1] +
                   ww.z * h2[4 * c4 + 2] + ww.w * h2[4 * c4 + 3];
        }
        #pragma unroll
        for (int c4 = 8; c4 < 16; c4++) {
            float4 ww = __ldg(&wp[c4]);
            int c = 4 * c4 - 32;
            acc += ww.x * gp[c] + ww.y * gp[c + 1] +
                   ww.z * gp[c + 2] + ww.w * gp[c + 3];
        }
        o1s[o][m] = fmaxf(fl_s1[o] * acc + fl_t1[o], 0.f);
    }
    __syncthreads();

    // fl2: out = W @ o1 + b
    #pragma unroll 2
    for (int o = 0; o < 64; o++) {
        float acc = fl_b2[o];
        const float4* wp = (const float4*)(fl_w2 + o * 64);
        #pragma unroll
        for (int c4 = 0; c4 < 16; c4++) {
            float4 ww = __ldg(&wp[c4]);
            acc += ww.x * o1s[4 * c4 + 0][m] + ww.y * o1s[4 * c4 + 1][m] +
                   ww.z * o1s[4 * c4 + 2][m] + ww.w * o1s[4 * c4 + 3][m];
        }
        out[((size_t)b * 64 + o) * NM + m] = acc;
    }
}

extern "C" void kernel_launch(void* const* d_in, const int* in_sizes, int n_in,
                              void* d_out, int out_size)
{
    const float* x_label      = (const float*)d_in[0];
    const float* x_object     = (const float*)d_in[1];
    const float* template_xyz = (const float*)d_in[2];
    const float* mlp_w1 = (const float*)d_in[3];
    const float* mlp_s1 = (const float*)d_in[4];
    const float* mlp_t1 = (const float*)d_in[5];
    const float* mlp_w2 = (const float*)d_in[6];
    const float* mlp_s2 = (const float*)d_in[7];
    const float* mlp_t2 = (const float*)d_in[8];
    const float* gw_w1  = (const float*)d_in[9];
    const float* gw_b1  = (const float*)d_in[10];
    const float* gw_s   = (const float*)d_in[11];
    const float* gw_t   = (const float*)d_in[12];
    const float* gw_w2  = (const float*)d_in[13];
    const float* gw_b2  = (const float*)d_in[14];
    const float* gm_w1  = (const float*)d_in[15];
    const float* gm_s1  = (const float*)d_in[16];
    const float* gm_t1  = (const float*)d_in[17];
    const float* gm_w2  = (const float*)d_in[18];
    const float* gm_s2  = (const float*)d_in[19];
    const float* gm_t2  = (const float*)d_in[20];
    const float* fl_w1  = (const float*)d_in[21];
    const float* fl_s1  = (const float*)d_in[22];
    const float* fl_t1  = (const float*)d_in[23];
    const float* fl_w2  = (const float*)d_in[24];
    const float* fl_b2  = (const float*)d_in[25];

    k_gpool<<<512, 128>>>(x_label, x_object, template_xyz,
                          gw_w1, gw_b1, gw_s, gw_t, gw_w2, gw_b2,
                          gm_w1, gm_s1, gm_t1, gm_w2, gm_s2, gm_t2);
    k_out<<<128, 128>>>(x_label, x_object, template_xyz,
                        mlp_w1, mlp_s1, mlp_t1, mlp_w2, mlp_s2, mlp_t2,
                        fl_w1, fl_s1, fl_t1, fl_w2, fl_b2, (float*)d_out);
}

// round 6
// speedup vs baseline: 1.4229x; 1.0022x over previous
#include <cuda_runtime.h>

#define BB 128
#define NT 64    // n1: templates
#define NM 128   // n2: label points

// scratch (device globals are sanctioned for scratch)
__device__ float g_gpool[BB * 32 * NM];

typedef unsigned long long ull;

__device__ __forceinline__ ull pk(float lo, float hi) {
    ull r; asm("mov.b64 %0,{%1,%2};" : "=l"(r) : "f"(lo), "f"(hi)); return r;
}
__device__ __forceinline__ ull pk1(float v) {
    ull r; asm("mov.b64 %0,{%1,%1};" : "=l"(r) : "f"(v)); return r;
}
__device__ __forceinline__ void upk(ull v, float& lo, float& hi) {
    asm("mov.b64 {%0,%1},%2;" : "=f"(lo), "=f"(hi) : "l"(v));
}
__device__ __forceinline__ ull ffma2(ull a, ull b, ull c) {
    ull d; asm("fma.rn.f32x2 %0,%1,%2,%3;" : "=l"(d) : "l"(a), "l"(b), "l"(c)); return d;
}

// ---------------------------------------------------------------------------
// Kernel 1: global-attention branch -> g_gpool (B,32,NM)
// grid 512 = B*4 m-tiles of 32. block 128 = 4 warps; warp w handles
// m_local = w*8+mi; lane = output channel o; 8 n-pixels per chunk packed
// into f32x2 pairs; weight columns in registers.
// ---------------------------------------------------------------------------
__global__ __launch_bounds__(128) void k_gpool(
    const float* __restrict__ x_label, const float* __restrict__ x_object,
    const float* __restrict__ template_xyz,
    const float* __restrict__ gw_w1, const float* __restrict__ gw_b1,
    const float* __restrict__ gw_s,  const float* __restrict__ gw_t,
    const float* __restrict__ gw_w2, const float* __restrict__ gw_b2,
    const float* __restrict__ gm_w1, const float* __restrict__ gm_s1,
    const float* __restrict__ gm_t1, const float* __restrict__ gm_w2,
    const float* __restrict__ gm_s2, const float* __restrict__ gm_t2)
{
    __shared__ float xoT[64][33];     // [n][c] padded
    __shared__ float Bn[64][33];      // [n][o] = -s*(W1@xo)
    __shared__ float Tn[64][33];      // [n][o] gm1 xyz part + t1
    __shared__ float As[32][33];      // [ml][o] = s*(W1@xl + b1) + t
    __shared__ float Wst[3][32][32];  // staging [layer][c][o]
    __shared__ float xls[32][32];
    __shared__ __align__(16) float buf[4][32][8];  // per-warp exchange, 8 px
    __shared__ float b2s[32], ct2s[32];

    const int tid = threadIdx.x;
    const int b = blockIdx.x >> 2, mt = blockIdx.x & 3;

    // ---- stage inputs + weights (coalesced) ----
    for (int i = tid; i < 2048; i += 128) {
        int c = i >> 6, n = i & 63;
        xoT[n][c] = x_object[(size_t)b * 2048 + i];
    }
    for (int i = tid; i < 1024; i += 128) {
        int c = i >> 5, ml = i & 31;
        xls[c][ml] = x_label[(size_t)b * 4096 + c * 128 + mt * 32 + ml];
    }
    for (int i = tid; i < 1024; i += 128) {
        int c = i >> 5, o = i & 31;
        Wst[0][c][o] = gw_w2[o * 32 + c];
        Wst[1][c][o] = gm_s1[o] * gm_w1[o * 35 + 3 + c];
        Wst[2][c][o] = gm_s2[o] * gm_w2[o * 32 + c];
    }
    if (tid < 32) { b2s[tid] = gw_b2[tid]; ct2s[tid] = gm_t2[tid]; }
    __syncthreads();

    // ---- per-(b,n) and per-(b,m) precompute ----
    for (int i = tid; i < 2048; i += 128) {
        int o = i >> 6, n = i & 63;
        float a = 0.f;
        #pragma unroll
        for (int c = 0; c < 32; c++) a += gw_w1[o * 32 + c] * xoT[n][c];
        Bn[n][o] = -gw_s[o] * a;
        const float* tx = template_xyz + (size_t)b * 192 + n * 3;
        Tn[n][o] = gm_s1[o] * (gm_w1[o * 35] * tx[0] + gm_w1[o * 35 + 1] * tx[1] +
                               gm_w1[o * 35 + 2] * tx[2]) + gm_t1[o];
    }
    for (int i = tid; i < 1024; i += 128) {
        int o = i >> 5, ml = i & 31;
        float a = 0.f;
        #pragma unroll
        for (int c = 0; c < 32; c++) a += gw_w1[o * 32 + c] * xls[c][ml];
        As[ml][o] = gw_s[o] * a + gw_s[o] * gw_b1[o] + gw_t[o];
    }
    __syncthreads();

    // ---- weight columns to registers (const-indexed only) ----
    const int w = tid >> 5, o = tid & 31;
    float w2r[32], wm1r[32], wm2r[32];
    #pragma unroll
    for (int c = 0; c < 32; c++) {
        w2r[c]  = Wst[0][c][o];
        wm1r[c] = Wst[1][c][o];
        wm2r[c] = Wst[2][c][o];
    }
    const float bias2 = b2s[o], biasT = ct2s[o];

    float4* mb = (float4*)&buf[w][o][0];

    #pragma unroll 1
    for (int mi = 0; mi < 8; mi++) {
        const int ml = w * 8 + mi;
        const float as = As[ml][o];
        float um = 0.f;

        #pragma unroll 1
        for (int j = 0; j < 8; j++) {
            const int n0 = 8 * j;

            // stage gw1 (folded): leaky(as + Bn[n][o]) for 8 pixels
            float L[8];
            #pragma unroll
            for (int i = 0; i < 8; i++) {
                float z = as + Bn[n0 + i][o];
                L[i] = fmaxf(z, 0.2f * z);
            }
            __syncwarp();
            mb[0] = make_float4(L[0], L[1], L[2], L[3]);
            mb[1] = make_float4(L[4], L[5], L[6], L[7]);
            __syncwarp();

            // stage gw2: q = b2 + W2 @ lv (4 packed pairs)
            ull q0 = pk1(bias2), q1 = q0, q2 = q0, q3 = q0;
            #pragma unroll
            for (int c = 0; c < 32; c++) {
                ull wp = pk1(w2r[c]);
                const ulonglong2* pv = (const ulonglong2*)&buf[w][c][0];
                ulonglong2 va = pv[0], vb = pv[1];
                q0 = ffma2(va.x, wp, q0); q1 = ffma2(va.y, wp, q1);
                q2 = ffma2(vb.x, wp, q2); q3 = ffma2(vb.y, wp, q3);
            }

            // gate: g = sigmoid(q) * xo[n][o]
            float qv[8];
            upk(q0, qv[0], qv[1]); upk(q1, qv[2], qv[3]);
            upk(q2, qv[4], qv[5]); upk(q3, qv[6], qv[7]);
            float G[8];
            #pragma unroll
            for (int i = 0; i < 8; i++)
                G[i] = __fdividef(xoT[n0 + i][o], 1.f + __expf(-qv[i]));
            __syncwarp();
            mb[0] = make_float4(G[0], G[1], G[2], G[3]);
            mb[1] = make_float4(G[4], G[5], G[6], G[7]);
            __syncwarp();

            // stage gm1: t = Tn + Wm1 @ g
            ull t0 = pk(Tn[n0 + 0][o], Tn[n0 + 1][o]);
            ull t1 = pk(Tn[n0 + 2][o], Tn[n0 + 3][o]);
            ull t2 = pk(Tn[n0 + 4][o], Tn[n0 + 5][o]);
            ull t3 = pk(Tn[n0 + 6][o], Tn[n0 + 7][o]);
            #pragma unroll
            for (int c = 0; c < 32; c++) {
                ull wp = pk1(wm1r[c]);
                const ulonglong2* pv = (const ulonglong2*)&buf[w][c][0];
                ulonglong2 va = pv[0], vb = pv[1];
                t0 = ffma2(va.x, wp, t0); t1 = ffma2(va.y, wp, t1);
                t2 = ffma2(vb.x, wp, t2); t3 = ffma2(vb.y, wp, t3);
            }
            float tv[8];
            upk(t0, tv[0], tv[1]); upk(t1, tv[2], tv[3]);
            upk(t2, tv[4], tv[5]); upk(t3, tv[6], tv[7]);
            __syncwarp();
            mb[0] = make_float4(fmaxf(tv[0], 0.f), fmaxf(tv[1], 0.f),
                                fmaxf(tv[2], 0.f), fmaxf(tv[3], 0.f));
            mb[1] = make_float4(fmaxf(tv[4], 0.f), fmaxf(tv[5], 0.f),
                                fmaxf(tv[6], 0.f), fmaxf(tv[7], 0.f));
            __syncwarp();

            // stage gm2: u = t2b + Wm2 @ r ; relu+max folded into um
            ull u0 = pk1(biasT), u1 = u0, u2 = u0, u3 = u0;
            #pragma unroll
            for (int c = 0; c < 32; c++) {
                ull wp = pk1(wm2r[c]);
                const ulonglong2* pv = (const ulonglong2*)&buf[w][c][0];
                ulonglong2 va = pv[0], vb = pv[1];
                u0 = ffma2(va.x, wp, u0); u1 = ffma2(va.y, wp, u1);
                u2 = ffma2(vb.x, wp, u2); u3 = ffma2(vb.y, wp, u3);
            }
            float uv[8];
            upk(u0, uv[0], uv[1]); upk(u1, uv[2], uv[3]);
            upk(u2, uv[4], uv[5]); upk(u3, uv[6], uv[7]);
            um = fmaxf(um, fmaxf(fmaxf(fmaxf(uv[0], uv[1]), fmaxf(uv[2], uv[3])),
                                 fmaxf(fmaxf(uv[4], uv[5]), fmaxf(uv[6], uv[7]))));
        }

        g_gpool[((size_t)b * 32 + o) * NM + mt * 32 + ml] = um;
    }
}

// ---------------------------------------------------------------------------
// Kernel 2: cosine sim + argmax gather + MLP + final layers -> out
// grid 512 = B*4 m-tiles of 32; block 128: ml = tid&31 (m in tile),
// p = tid>>5 (4 parts splitting n-scan / output channels).
// ---------------------------------------------------------------------------
__global__ __launch_bounds__(128) void k_out(
    const float* __restrict__ x_label, const float* __restrict__ x_object,
    const float* __restrict__ template_xyz,
    const float* __restrict__ mlp_w1, const float* __restrict__ mlp_s1,
    const float* __restrict__ mlp_t1, const float* __restrict__ mlp_w2,
    const float* __restrict__ mlp_s2, const float* __restrict__ mlp_t2,
    const float* __restrict__ fl_w1, const float* __restrict__ fl_s1,
    const float* __restrict__ fl_t1, const float* __restrict__ fl_w2,
    const float* __restrict__ fl_b2, float* __restrict__ out)
{
    __shared__ float xo_s[32][64];
    __shared__ float w1T[68][32];
    __shared__ float w2T[32][32];
    __shared__ float na_s[64];
    __shared__ float hs[32][33];   // [ml][c] MLP hidden
    __shared__ float fu[64][33];   // [c][ml]: 0..31 = h2, 32..63 = gpool
    __shared__ float o1s[64][33];  // [o][ml]
    __shared__ float sb[4][32];
    __shared__ int   si[4][32];

    const int b = blockIdx.x >> 2, mt = blockIdx.x & 3;
    const int tid = threadIdx.x, ml = tid & 31, p = tid >> 5;
    const int m = mt * 32 + ml;

    for (int i = tid; i < 2048; i += 128)
        ((float*)xo_s)[i] = x_object[(size_t)b * 2048 + i];
    for (int i = tid; i < 68 * 32; i += 128) {
        int j = i >> 5, o = i & 31;
        w1T[j][o] = mlp_w1[o * 68 + j];
    }
    for (int i = tid; i < 1024; i += 128) {
        int c = i >> 5, o = i & 31;
        w2T[c][o] = mlp_w2[o * 32 + c];
    }
    for (int i = tid; i < 1024; i += 128) {   // gpool slice -> fu[32+c][q]
        int c = i >> 5, q = i & 31;
        fu[32 + c][q] = g_gpool[((size_t)b * 32 + c) * NM + mt * 32 + q];
    }
    __syncthreads();
    if (tid < 64) {
        float s = 0.f;
        #pragma unroll
        for (int c = 0; c < 32; c++) { float v = xo_s[c][tid]; s += v * v; }
        na_s[tid] = sqrtf(s);
    }

    float xl[32];
    #pragma unroll
    for (int c = 0; c < 32; c++)
        xl[c] = x_label[(size_t)b * 4096 + c * 128 + m];
    float nb = 0.f;
    #pragma unroll
    for (int c = 0; c < 32; c++) nb += xl[c] * xl[c];
    nb = sqrtf(nb);
    __syncthreads();

    // argmax over n in [16p, 16p+16), then combine parts (first-max kept)
    float best = -3.4e38f; int bidx = 16 * p;
    #pragma unroll 1
    for (int n = 16 * p; n < 16 * p + 16; n++) {
        float num = 0.f;
        #pragma unroll
        for (int c = 0; c < 32; c++) num += xo_s[c][n] * xl[c];
        float cs = num / fmaxf(na_s[n] * nb, 1e-8f);
        if (cs > best) { best = cs; bidx = n; }
    }
    sb[p][ml] = best; si[p][ml] = bidx;
    __syncthreads();
    best = sb[0][ml]; bidx = si[0][ml];
    #pragma unroll
    for (int pp = 1; pp < 4; pp++)
        if (sb[pp][ml] > best) { best = sb[pp][ml]; bidx = si[pp][ml]; }

    // h for o in [8p, 8p+8): relu(s1*(W1 @ [best, txyz, xo[:,bidx], xl]) + t1)
    float hr[8];
    {
        const float* tx = template_xyz + (size_t)b * 192 + bidx * 3;
        float a0 = tx[0], a1 = tx[1], a2 = tx[2];
        #pragma unroll
        for (int oo = 0; oo < 8; oo++) {
            int o = 8 * p + oo;
            hr[oo] = w1T[0][o] * best + w1T[1][o] * a0 +
                     w1T[2][o] * a1 + w1T[3][o] * a2;
        }
    }
    #pragma unroll
    for (int c = 0; c < 32; c++) {
        float xoc = xo_s[c][bidx];
        #pragma unroll
        for (int oo = 0; oo < 8; oo++) hr[oo] += w1T[4 + c][8 * p + oo] * xoc;
    }
    #pragma unroll
    for (int c = 0; c < 32; c++) {
        float v = xl[c];
        #pragma unroll
        for (int oo = 0; oo < 8; oo++) hr[oo] += w1T[36 + c][8 * p + oo] * v;
    }
    #pragma unroll
    for (int oo = 0; oo < 8; oo++) {
        int o = 8 * p + oo;
        hs[ml][o] = fmaxf(mlp_s1[o] * hr[oo] + mlp_t1[o], 0.f);
    }
    __syncthreads();

    // h2 for o in [8p, 8p+8) -> fu[o][ml]
    float h2r[8];
    #pragma unroll
    for (int oo = 0; oo < 8; oo++) h2r[oo] = 0.f;
    #pragma unroll
    for (int c = 0; c < 32; c++) {
        float v = hs[ml][c];
        #pragma unroll
        for (int oo = 0; oo < 8; oo++) h2r[oo] += w2T[c][8 * p + oo] * v;
    }
    #pragma unroll
    for (int oo = 0; oo < 8; oo++) {
        int o = 8 * p + oo;
        fu[o][ml] = fmaxf(mlp_s2[o] * h2r[oo] + mlp_t2[o], 0.f);
    }
    __syncthreads();

    // fl1 for o in [16p, 16p+16): inputs hoisted to registers
    float fv[64];
    #pragma unroll
    for (int c = 0; c < 64; c++) fv[c] = fu[c][ml];
    #pragma unroll 4
    for (int oo = 0; oo < 16; oo++) {
        int o = 16 * p + oo;
        float acc = 0.f;
        const float4* wp4 = (const float4*)(fl_w1 + o * 64);
        #pragma unroll
        for (int c4 = 0; c4 < 16; c4++) {
            float4 ww = __ldg(&wp4[c4]);
            acc += ww.x * fv[4 * c4] + ww.y * fv[4 * c4 + 1] +
                   ww.z * fv[4 * c4 + 2] + ww.w * fv[4 * c4 + 3];
        }
        o1s[o][ml] = fmaxf(fl_s1[o] * acc + fl_t1[o], 0.f);
    }
    __syncthreads();

    // fl2 for o in [16p, 16p+16)
    float ov[64];
    #pragma unroll
    for (int c = 0; c < 64; c++) ov[c] = o1s[c][ml];
    #pragma unroll 4
    for (int oo = 0; oo < 16; oo++) {
        int o = 16 * p + oo;
        float acc = fl_b2[o];
        const float4* wp4 = (const float4*)(fl_w2 + o * 64);
        #pragma unroll
        for (int c4 = 0; c4 < 16; c4++) {
            float4 ww = __ldg(&wp4[c4]);
            acc += ww.x * ov[4 * c4] + ww.y * ov[4 * c4 + 1] +
                   ww.z * ov[4 * c4 + 2] + ww.w * ov[4 * c4 + 3];
        }
        out[((size_t)b * 64 + o) * NM + m] = acc;
    }
}

extern "C" void kernel_launch(void* const* d_in, const int* in_sizes, int n_in,
                              void* d_out, int out_size)
{
    const float* x_label      = (const float*)d_in[0];
    const float* x_object     = (const float*)d_in[1];
    const float* template_xyz = (const float*)d_in[2];
    const float* mlp_w1 = (const float*)d_in[3];
    const float* mlp_s1 = (const float*)d_in[4];
    const float* mlp_t1 = (const float*)d_in[5];
    const float* mlp_w2 = (const float*)d_in[6];
    const float* mlp_s2 = (const float*)d_in[7];
    const float* mlp_t2 = (const float*)d_in[8];
    const float* gw_w1  = (const float*)d_in[9];
    const float* gw_b1  = (const float*)d_in[10];
    const float* gw_s   = (const float*)d_in[11];
    const float* gw_t   = (const float*)d_in[12];
    const float* gw_w2  = (const float*)d_in[13];
    const float* gw_b2  = (const float*)d_in[14];
    const float* gm_w1  = (const float*)d_in[15];
    const float* gm_s1  = (const float*)d_in[16];
    const float* gm_t1  = (const float*)d_in[17];
    const float* gm_w2  = (const float*)d_in[18];
    const float* gm_s2  = (const float*)d_in[19];
    const float* gm_t2  = (const float*)d_in[20];
    const float* fl_w1  = (const float*)d_in[21];
    const float* fl_s1  = (const float*)d_in[22];
    const float* fl_t1  = (const float*)d_in[23];
    const float* fl_w2  = (const float*)d_in[24];
    const float* fl_b2  = (const float*)d_in[25];

    k_gpool<<<512, 128>>>(x_label, x_object, template_xyz,
                          gw_w1, gw_b1, gw_s, gw_t, gw_w2, gw_b2,
                          gm_w1, gm_s1, gm_t1, gm_w2, gm_s2, gm_t2);
    k_out<<<512, 128>>>(x_label, x_object, template_xyz,
                        mlp_w1, mlp_s1, mlp_t1, mlp_w2, mlp_s2, mlp_t2,
                        fl_w1, fl_s1, fl_t1, fl_w2, fl_b2, (float*)d_out);
}

// round 7
// speedup vs baseline: 1.4705x; 1.0334x over previous
#include <cuda_runtime.h>

#define BB 128
#define NT 64    // n1: templates
#define NM 128   // n2: label points

// scratch (device globals are sanctioned for scratch)
__device__ float g_gpool[BB * 32 * NM];

typedef unsigned long long ull;

__device__ __forceinline__ ull pk(float lo, float hi) {
    ull r; asm("mov.b64 %0,{%1,%2};" : "=l"(r) : "f"(lo), "f"(hi)); return r;
}
__device__ __forceinline__ ull pk1(float v) {
    ull r; asm("mov.b64 %0,{%1,%1};" : "=l"(r) : "f"(v)); return r;
}
__device__ __forceinline__ void upk(ull v, float& lo, float& hi) {
    asm("mov.b64 {%0,%1},%2;" : "=f"(lo), "=f"(hi) : "l"(v));
}
__device__ __forceinline__ ull ffma2(ull a, ull b, ull c) {
    ull d; asm("fma.rn.f32x2 %0,%1,%2,%3;" : "=l"(d) : "l"(a), "l"(b), "l"(c)); return d;
}

// ---------------------------------------------------------------------------
// Kernel 1: global-attention branch -> g_gpool (B,32,NM)
// grid 512 = B*4 m-tiles of 32. block 128 = 4 warps; warp w owns ml in
// [8w, 8w+8) processed as 4 (ml0,ml1) PAIRS; lane = output channel o.
// Each f32x2 packs the SAME n for the two m's -> weight splats, Bn/Tn/xoT
// loads amortized over 8 pixels. Triple-buffered per-warp exchange:
// 3 syncwarps per 8-pixel chunk.
// ---------------------------------------------------------------------------
__global__ __launch_bounds__(128) void k_gpool(
    const float* __restrict__ x_label, const float* __restrict__ x_object,
    const float* __restrict__ template_xyz,
    const float* __restrict__ gw_w1, const float* __restrict__ gw_b1,
    const float* __restrict__ gw_s,  const float* __restrict__ gw_t,
    const float* __restrict__ gw_w2, const float* __restrict__ gw_b2,
    const float* __restrict__ gm_w1, const float* __restrict__ gm_s1,
    const float* __restrict__ gm_t1, const float* __restrict__ gm_w2,
    const float* __restrict__ gm_s2, const float* __restrict__ gm_t2)
{
    __shared__ float xoT[64][33];     // [n][c] padded
    __shared__ float Bn[64][33];      // [n][o] = -s*(W1@xo)
    __shared__ float Tn[64][33];      // [n][o] gm1 xyz part + t1
    __shared__ float As[32][33];      // [ml][o] = s*(W1@xl + b1) + t
    __shared__ float xls[32][32];
    __shared__ float b2s[32], ct2s[32];
    // exchange buffers; double as weight staging (each = 4KB = 32x32 floats)
    __shared__ __align__(16) ull bufL[4][32][4];
    __shared__ __align__(16) ull bufG[4][32][4];
    __shared__ __align__(16) ull bufT[4][32][4];

    float* Wst0 = (float*)&bufL[0][0][0];   // gw_w2^T
    float* Wst1 = (float*)&bufG[0][0][0];   // gm_w1^T scaled
    float* Wst2 = (float*)&bufT[0][0][0];   // gm_w2^T scaled

    const int tid = threadIdx.x;
    const int b = blockIdx.x >> 2, mt = blockIdx.x & 3;

    // ---- stage inputs + weights ----
    for (int i = tid; i < 2048; i += 128) {
        int c = i >> 6, n = i & 63;
        xoT[n][c] = x_object[(size_t)b * 2048 + i];
    }
    for (int i = tid; i < 1024; i += 128) {
        int c = i >> 5, ml = i & 31;
        xls[c][ml] = x_label[(size_t)b * 4096 + c * 128 + mt * 32 + ml];
    }
    for (int i = tid; i < 1024; i += 128) {
        int c = i >> 5, o = i & 31;
        Wst0[c * 32 + o] = gw_w2[o * 32 + c];
        Wst1[c * 32 + o] = gm_s1[o] * gm_w1[o * 35 + 3 + c];
        Wst2[c * 32 + o] = gm_s2[o] * gm_w2[o * 32 + c];
    }
    if (tid < 32) { b2s[tid] = gw_b2[tid]; ct2s[tid] = gm_t2[tid]; }
    __syncthreads();

    // ---- per-(b,n) and per-(b,m) precompute ----
    for (int i = tid; i < 2048; i += 128) {
        int o = i >> 6, n = i & 63;
        float a = 0.f;
        #pragma unroll
        for (int c = 0; c < 32; c++) a += gw_w1[o * 32 + c] * xoT[n][c];
        Bn[n][o] = -gw_s[o] * a;
        const float* tx = template_xyz + (size_t)b * 192 + n * 3;
        Tn[n][o] = gm_s1[o] * (gm_w1[o * 35] * tx[0] + gm_w1[o * 35 + 1] * tx[1] +
                               gm_w1[o * 35 + 2] * tx[2]) + gm_t1[o];
    }
    for (int i = tid; i < 1024; i += 128) {
        int o = i >> 5, ml = i & 31;
        float a = 0.f;
        #pragma unroll
        for (int c = 0; c < 32; c++) a += gw_w1[o * 32 + c] * xls[c][ml];
        As[ml][o] = gw_s[o] * a + gw_s[o] * gw_b1[o] + gw_t[o];
    }
    __syncthreads();

    // ---- weight columns to registers (const-indexed only) ----
    const int w = tid >> 5, o = tid & 31;
    float w2r[32], wm1r[32], wm2r[32];
    #pragma unroll
    for (int c = 0; c < 32; c++) {
        w2r[c]  = Wst0[c * 32 + o];
        wm1r[c] = Wst1[c * 32 + o];
        wm2r[c] = Wst2[c * 32 + o];
    }
    const float bias2 = b2s[o], biasT = ct2s[o];
    __syncthreads();   // staging region becomes exchange buffers below

    #pragma unroll 1
    for (int t = 0; t < 4; t++) {
        const int ml0 = w * 8 + 2 * t, ml1 = ml0 + 1;
        const float as0 = As[ml0][o], as1 = As[ml1][o];
        float um0 = 0.f, um1 = 0.f;

        #pragma unroll 1
        for (int j = 0; j < 16; j++) {
            const int n0 = 4 * j;

            // gw1 (folded) + leaky, packed (ml0, ml1) per n
            ull Lp0, Lp1, Lp2, Lp3;
            {
                float bn0 = Bn[n0 + 0][o], bn1 = Bn[n0 + 1][o];
                float bn2 = Bn[n0 + 2][o], bn3 = Bn[n0 + 3][o];
                float za, zb;
                za = as0 + bn0; zb = as1 + bn0;
                Lp0 = pk(fmaxf(za, 0.2f * za), fmaxf(zb, 0.2f * zb));
                za = as0 + bn1; zb = as1 + bn1;
                Lp1 = pk(fmaxf(za, 0.2f * za), fmaxf(zb, 0.2f * zb));
                za = as0 + bn2; zb = as1 + bn2;
                Lp2 = pk(fmaxf(za, 0.2f * za), fmaxf(zb, 0.2f * zb));
                za = as0 + bn3; zb = as1 + bn3;
                Lp3 = pk(fmaxf(za, 0.2f * za), fmaxf(zb, 0.2f * zb));
            }
            *(ulonglong2*)&bufL[w][o][0] = make_ulonglong2(Lp0, Lp1);
            *(ulonglong2*)&bufL[w][o][2] = make_ulonglong2(Lp2, Lp3);
            __syncwarp();

            // gw2: q = b2 + W2 @ L
            ull q0 = pk1(bias2), q1 = q0, q2 = q0, q3 = q0;
            #pragma unroll
            for (int c = 0; c < 32; c++) {
                ull wp = pk1(w2r[c]);
                ulonglong2 va = *(const ulonglong2*)&bufL[w][c][0];
                ulonglong2 vb = *(const ulonglong2*)&bufL[w][c][2];
                q0 = ffma2(va.x, wp, q0); q1 = ffma2(va.y, wp, q1);
                q2 = ffma2(vb.x, wp, q2); q3 = ffma2(vb.y, wp, q3);
            }

            // gate: g = sigmoid(q) * xo[n][o]  (xo shared by both m's)
            {
                float qa, qb, xo;
                upk(q0, qa, qb); xo = xoT[n0 + 0][o];
                q0 = pk(__fdividef(xo, 1.f + __expf(-qa)),
                        __fdividef(xo, 1.f + __expf(-qb)));
                upk(q1, qa, qb); xo = xoT[n0 + 1][o];
                q1 = pk(__fdividef(xo, 1.f + __expf(-qa)),
                        __fdividef(xo, 1.f + __expf(-qb)));
                upk(q2, qa, qb); xo = xoT[n0 + 2][o];
                q2 = pk(__fdividef(xo, 1.f + __expf(-qa)),
                        __fdividef(xo, 1.f + __expf(-qb)));
                upk(q3, qa, qb); xo = xoT[n0 + 3][o];
                q3 = pk(__fdividef(xo, 1.f + __expf(-qa)),
                        __fdividef(xo, 1.f + __expf(-qb)));
            }
            *(ulonglong2*)&bufG[w][o][0] = make_ulonglong2(q0, q1);
            *(ulonglong2*)&bufG[w][o][2] = make_ulonglong2(q2, q3);
            __syncwarp();

            // gm1: t = Tn + Wm1 @ g (Tn shared by both m's)
            ull t0 = pk1(Tn[n0 + 0][o]), t1 = pk1(Tn[n0 + 1][o]);
            ull t2 = pk1(Tn[n0 + 2][o]), t3 = pk1(Tn[n0 + 3][o]);
            #pragma unroll
            for (int c = 0; c < 32; c++) {
                ull wp = pk1(wm1r[c]);
                ulonglong2 va = *(const ulonglong2*)&bufG[w][c][0];
                ulonglong2 vb = *(const ulonglong2*)&bufG[w][c][2];
                t0 = ffma2(va.x, wp, t0); t1 = ffma2(va.y, wp, t1);
                t2 = ffma2(vb.x, wp, t2); t3 = ffma2(vb.y, wp, t3);
            }
            {
                float ta, tb;
                upk(t0, ta, tb); t0 = pk(fmaxf(ta, 0.f), fmaxf(tb, 0.f));
                upk(t1, ta, tb); t1 = pk(fmaxf(ta, 0.f), fmaxf(tb, 0.f));
                upk(t2, ta, tb); t2 = pk(fmaxf(ta, 0.f), fmaxf(tb, 0.f));
                upk(t3, ta, tb); t3 = pk(fmaxf(ta, 0.f), fmaxf(tb, 0.f));
            }
            *(ulonglong2*)&bufT[w][o][0] = make_ulonglong2(t0, t1);
            *(ulonglong2*)&bufT[w][o][2] = make_ulonglong2(t2, t3);
            __syncwarp();

            // gm2: u = t2b + Wm2 @ r ; relu+max folded into um
            ull u0 = pk1(biasT), u1 = u0, u2 = u0, u3 = u0;
            #pragma unroll
            for (int c = 0; c < 32; c++) {
                ull wp = pk1(wm2r[c]);
                ulonglong2 va = *(const ulonglong2*)&bufT[w][c][0];
                ulonglong2 vb = *(const ulonglong2*)&bufT[w][c][2];
                u0 = ffma2(va.x, wp, u0); u1 = ffma2(va.y, wp, u1);
                u2 = ffma2(vb.x, wp, u2); u3 = ffma2(vb.y, wp, u3);
            }
            {
                float ua, ub;
                upk(u0, ua, ub); um0 = fmaxf(um0, ua); um1 = fmaxf(um1, ub);
                upk(u1, ua, ub); um0 = fmaxf(um0, ua); um1 = fmaxf(um1, ub);
                upk(u2, ua, ub); um0 = fmaxf(um0, ua); um1 = fmaxf(um1, ub);
                upk(u3, ua, ub); um0 = fmaxf(um0, ua); um1 = fmaxf(um1, ub);
            }
        }

        g_gpool[((size_t)b * 32 + o) * NM + mt * 32 + ml0] = um0;
        g_gpool[((size_t)b * 32 + o) * NM + mt * 32 + ml1] = um1;
    }
}

// ---------------------------------------------------------------------------
// Kernel 2: cosine sim + argmax gather + MLP + final layers -> out
// grid 512 = B*4 m-tiles of 32; block 256: ml = tid&31, p = tid>>5 (8 parts).
// ---------------------------------------------------------------------------
__global__ __launch_bounds__(256) void k_out(
    const float* __restrict__ x_label, const float* __restrict__ x_object,
    const float* __restrict__ template_xyz,
    const float* __restrict__ mlp_w1, const float* __restrict__ mlp_s1,
    const float* __restrict__ mlp_t1, const float* __restrict__ mlp_w2,
    const float* __restrict__ mlp_s2, const float* __restrict__ mlp_t2,
    const float* __restrict__ fl_w1, const float* __restrict__ fl_s1,
    const float* __restrict__ fl_t1, const float* __restrict__ fl_w2,
    const float* __restrict__ fl_b2, float* __restrict__ out)
{
    __shared__ float xo_s[32][64];
    __shared__ float w1T[68][32];
    __shared__ float w2T[32][32];
    __shared__ float na_s[64];
    __shared__ float hs[32][33];   // [ml][c] MLP hidden
    __shared__ float fu[64][33];   // [c][ml]: 0..31 = h2, 32..63 = gpool
    __shared__ float o1s[64][33];  // [o][ml]
    __shared__ float sb[8][32];
    __shared__ int   si[8][32];

    const int b = blockIdx.x >> 2, mt = blockIdx.x & 3;
    const int tid = threadIdx.x, ml = tid & 31, p = tid >> 5;
    const int m = mt * 32 + ml;

    for (int i = tid; i < 2048; i += 256)
        ((float*)xo_s)[i] = x_object[(size_t)b * 2048 + i];
    for (int i = tid; i < 68 * 32; i += 256) {
        int j = i >> 5, o = i & 31;
        w1T[j][o] = mlp_w1[o * 68 + j];
    }
    for (int i = tid; i < 1024; i += 256) {
        int c = i >> 5, o = i & 31;
        w2T[c][o] = mlp_w2[o * 32 + c];
    }
    for (int i = tid; i < 1024; i += 256) {   // gpool slice -> fu[32+c][q]
        int c = i >> 5, q = i & 31;
        fu[32 + c][q] = g_gpool[((size_t)b * 32 + c) * NM + mt * 32 + q];
    }
    __syncthreads();
    if (tid < 64) {
        float s = 0.f;
        #pragma unroll
        for (int c = 0; c < 32; c++) { float v = xo_s[c][tid]; s += v * v; }
        na_s[tid] = sqrtf(s);
    }

    float xl[32];
    #pragma unroll
    for (int c = 0; c < 32; c++)
        xl[c] = x_label[(size_t)b * 4096 + c * 128 + m];
    float nb = 0.f;
    #pragma unroll
    for (int c = 0; c < 32; c++) nb += xl[c] * xl[c];
    nb = sqrtf(nb);
    __syncthreads();

    // argmax over n in [8p, 8p+8), combine in part order (first-max kept)
    float best = -3.4e38f; int bidx = 8 * p;
    #pragma unroll 1
    for (int n = 8 * p; n < 8 * p + 8; n++) {
        float num = 0.f;
        #pragma unroll
        for (int c = 0; c < 32; c++) num += xo_s[c][n] * xl[c];
        float cs = num / fmaxf(na_s[n] * nb, 1e-8f);
        if (cs > best) { best = cs; bidx = n; }
    }
    sb[p][ml] = best; si[p][ml] = bidx;
    __syncthreads();
    best = sb[0][ml]; bidx = si[0][ml];
    #pragma unroll
    for (int pp = 1; pp < 8; pp++)
        if (sb[pp][ml] > best) { best = sb[pp][ml]; bidx = si[pp][ml]; }

    // h for o in [4p, 4p+4)
    float hr[4];
    {
        const float* tx = template_xyz + (size_t)b * 192 + bidx * 3;
        float a0 = tx[0], a1 = tx[1], a2 = tx[2];
        #pragma unroll
        for (int oo = 0; oo < 4; oo++) {
            int o = 4 * p + oo;
            hr[oo] = w1T[0][o] * best + w1T[1][o] * a0 +
                     w1T[2][o] * a1 + w1T[3][o] * a2;
        }
    }
    #pragma unroll
    for (int c = 0; c < 32; c++) {
        float xoc = xo_s[c][bidx];
        #pragma unroll
        for (int oo = 0; oo < 4; oo++) hr[oo] += w1T[4 + c][4 * p + oo] * xoc;
    }
    #pragma unroll
    for (int c = 0; c < 32; c++) {
        float v = xl[c];
        #pragma unroll
        for (int oo = 0; oo < 4; oo++) hr[oo] += w1T[36 + c][4 * p + oo] * v;
    }
    #pragma unroll
    for (int oo = 0; oo < 4; oo++) {
        int o = 4 * p + oo;
        hs[ml][o] = fmaxf(mlp_s1[o] * hr[oo] + mlp_t1[o], 0.f);
    }
    __syncthreads();

    // h2 for o in [4p, 4p+4) -> fu[o][ml]
    float h2r[4] = {0.f, 0.f, 0.f, 0.f};
    #pragma unroll
    for (int c = 0; c < 32; c++) {
        float v = hs[ml][c];
        #pragma unroll
        for (int oo = 0; oo < 4; oo++) h2r[oo] += w2T[c][4 * p + oo] * v;
    }
    #pragma unroll
    for (int oo = 0; oo < 4; oo++) {
        int o = 4 * p + oo;
        fu[o][ml] = fmaxf(mlp_s2[o] * h2r[oo] + mlp_t2[o], 0.f);
    }
    __syncthreads();

    // fl1 for o in [8p, 8p+8)
    float fv[64];
    #pragma unroll
    for (int c = 0; c < 64; c++) fv[c] = fu[c][ml];
    #pragma unroll 2
    for (int oo = 0; oo < 8; oo++) {
        int o = 8 * p + oo;
        float acc = 0.f;
        const float4* wp4 = (const float4*)(fl_w1 + o * 64);
        #pragma unroll
        for (int c4 = 0; c4 < 16; c4++) {
            float4 ww = __ldg(&wp4[c4]);
            acc += ww.x * fv[4 * c4] + ww.y * fv[4 * c4 + 1] +
                   ww.z * fv[4 * c4 + 2] + ww.w * fv[4 * c4 + 3];
        }
        o1s[o][ml] = fmaxf(fl_s1[o] * acc + fl_t1[o], 0.f);
    }
    __syncthreads();

    // fl2 for o in [8p, 8p+8)
    float ov[64];
    #pragma unroll
    for (int c = 0; c < 64; c++) ov[c] = o1s[c][ml];
    #pragma unroll 2
    for (int oo = 0; oo < 8; oo++) {
        int o = 8 * p + oo;
        float acc = fl_b2[o];
        const float4* wp4 = (const float4*)(fl_w2 + o * 64);
        #pragma unroll
        for (int c4 = 0; c4 < 16; c4++) {
            float4 ww = __ldg(&wp4[c4]);
            acc += ww.x * ov[4 * c4] + ww.y * ov[4 * c4 + 1] +
                   ww.z * ov[4 * c4 + 2] + ww.w * ov[4 * c4 + 3];
        }
        out[((size_t)b * 64 + o) * NM + m] = acc;
    }
}

extern "C" void kernel_launch(void* const* d_in, const int* in_sizes, int n_in,
                              void* d_out, int out_size)
{
    const float* x_label      = (const float*)d_in[0];
    const float* x_object     = (const float*)d_in[1];
    const float* template_xyz = (const float*)d_in[2];
    const float* mlp_w1 = (const float*)d_in[3];
    const float* mlp_s1 = (const float*)d_in[4];
    const float* mlp_t1 = (const float*)d_in[5];
    const float* mlp_w2 = (const float*)d_in[6];
    const float* mlp_s2 = (const float*)d_in[7];
    const float* mlp_t2 = (const float*)d_in[8];
    const float* gw_w1  = (const float*)d_in[9];
    const float* gw_b1  = (const float*)d_in[10];
    const float* gw_s   = (const float*)d_in[11];
    const float* gw_t   = (const float*)d_in[12];
    const float* gw_w2  = (const float*)d_in[13];
    const float* gw_b2  = (const float*)d_in[14];
    const float* gm_w1  = (const float*)d_in[15];
    const float* gm_s1  = (const float*)d_in[16];
    const float* gm_t1  = (const float*)d_in[17];
    const float* gm_w2  = (const float*)d_in[18];
    const float* gm_s2  = (const float*)d_in[19];
    const float* gm_t2  = (const float*)d_in[20];
    const float* fl_w1  = (const float*)d_in[21];
    const float* fl_s1  = (const float*)d_in[22];
    const float* fl_t1  = (const float*)d_in[23];
    const float* fl_w2  = (const float*)d_in[24];
    const float* fl_b2  = (const float*)d_in[25];

    k_gpool<<<512, 128>>>(x_label, x_object, template_xyz,
                          gw_w1, gw_b1, gw_s, gw_t, gw_w2, gw_b2,
                          gm_w1, gm_s1, gm_t1, gm_w2, gm_s2, gm_t2);
    k_out<<<512, 256>>>(x_label, x_object, template_xyz,
                        mlp_w1, mlp_s1, mlp_t1, mlp_w2, mlp_s2, mlp_t2,
                        fl_w1, fl_s1, fl_t1, fl_w2, fl_b2, (float*)d_out);
}